// round 15
// baseline (speedup 1.0000x reference)
#include <cuda_runtime.h>

// MomentumLIF: x[N,T,D] f32 -> spikes[N,T,D] f32
//   v_t = mom*v + x_t - lamb*u
//   u_t = 0.5*u + v_t        (decay = 1 - 1/tau, tau=2)
//   s_t = (u_t >= 1);  u_t = 0 if spiked (hard reset)
// One thread = 4 consecutive d (float4), serial over T=64 with u/v in regs.
//
// R14: read/write BURST GROUPING. Prior best (R8: cold 37.9us, DRAM 72.9%)
// interleaves 1 load + 1 store per timestep; HBM pays bus-turnaround on
// fine-grained R/W mixes. Restructure into 16 groups of 4 timesteps:
// burst-load the next group (double-buffered), compute 4 steps, burst-store
// 4 results. Each thread emits 512B same-direction bursts; warps together
// give the controller long homogeneous runs. Fully unrolled, ~64 regs,
// 3 blocks/SM (occupancy proven non-binding in R10).
// Cache policy: plain loads/stores (all hint variants measured slower).

#define LIF_N 64
#define LIF_T 64
#define LIF_D 8192
#define LIF_D4 (LIF_D / 4)          // 2048 float4 per row
#define THREADS 256
#define G 4                          // timesteps per group
#define NG (LIF_T / G)               // 16 groups

__global__ __launch_bounds__(THREADS, 3)
void momentum_lif_kernel(const float4* __restrict__ x,
                         const float* __restrict__ p_mom,
                         const float* __restrict__ p_lamb,
                         float4* __restrict__ out) {
    const float mom = __ldg(p_mom);
    const float lb  = __ldg(p_lamb);

    int idx = blockIdx.x * THREADS + threadIdx.x;   // 0 .. N*D4-1 (exact grid)
    int n  = idx >> 11;          // idx / 2048
    int d4 = idx & 2047;         // idx % 2048

    const float4* xp = x   + (size_t)n * LIF_T * LIF_D4 + d4;
    float4*       op = out + (size_t)n * LIF_T * LIF_D4 + d4;

    float ux = 0.f, uy = 0.f, uz = 0.f, uw = 0.f;
    float vx = 0.f, vy = 0.f, vz = 0.f, vw = 0.f;

    // Double-buffered group loads: burst G loads at a time.
    float4 xbuf[2][G];
#pragma unroll
    for (int i = 0; i < G; ++i)
        xbuf[0][i] = xp[(size_t)i * LIF_D4];

#pragma unroll
    for (int g = 0; g < NG; ++g) {
        const int cur = g & 1;
        const int nxt = cur ^ 1;

        // Burst-prefetch the next group's 4 loads before touching this
        // group's data (independent of the recurrence chain).
        if (g + 1 < NG) {
#pragma unroll
            for (int i = 0; i < G; ++i)
                xbuf[nxt][i] = xp[(size_t)((g + 1) * G + i) * LIF_D4];
        }

        float4 s[G];
#pragma unroll
        for (int tt = 0; tt < G; ++tt) {
            float4 xv = xbuf[cur][tt];

            // lane x
            vx = fmaf(mom, vx, xv.x);
            vx = fmaf(-lb, ux, vx);
            ux = fmaf(0.5f, ux, vx);
            float sx = (ux >= 1.0f) ? 1.0f : 0.0f;
            ux = (ux >= 1.0f) ? 0.0f : ux;
            // lane y
            vy = fmaf(mom, vy, xv.y);
            vy = fmaf(-lb, uy, vy);
            uy = fmaf(0.5f, uy, vy);
            float sy = (uy >= 1.0f) ? 1.0f : 0.0f;
            uy = (uy >= 1.0f) ? 0.0f : uy;
            // lane z
            vz = fmaf(mom, vz, xv.z);
            vz = fmaf(-lb, uz, vz);
            uz = fmaf(0.5f, uz, vz);
            float sz = (uz >= 1.0f) ? 1.0f : 0.0f;
            uz = (uz >= 1.0f) ? 0.0f : uz;
            // lane w
            vw = fmaf(mom, vw, xv.w);
            vw = fmaf(-lb, uw, vw);
            uw = fmaf(0.5f, uw, vw);
            float sw = (uw >= 1.0f) ? 1.0f : 0.0f;
            uw = (uw >= 1.0f) ? 0.0f : uw;

            s[tt] = make_float4(sx, sy, sz, sw);
        }

        // Burst-store the group's 4 results.
#pragma unroll
        for (int tt = 0; tt < G; ++tt)
            op[(size_t)(g * G + tt) * LIF_D4] = s[tt];
    }
}

extern "C" void kernel_launch(void* const* d_in, const int* in_sizes, int n_in,
                              void* d_out, int out_size) {
    const float4* x      = (const float4*)d_in[0];
    const float*  p_mom  = (const float*)d_in[1];
    const float*  p_lamb = (const float*)d_in[2];
    float4*       out    = (float4*)d_out;

    const int total = LIF_N * LIF_D4;           // 131072 threads
    momentum_lif_kernel<<<total / THREADS, THREADS>>>(x, p_mom, p_lamb, out);
}

// round 16
// speedup vs baseline: 1.0348x; 1.0348x over previous
#include <cuda_runtime.h>

// MomentumLIF: x[N,T,D] f32 -> spikes[N,T,D] f32
//   v_t = mom*v + x_t - lamb*u
//   u_t = 0.5*u + v_t        (decay = 1 - 1/tau, tau=2)
//   s_t = (u_t >= 1);  u_t = 0 if spiked (hard reset)
// One thread = 4 consecutive d (float4), serial over T=64 with u/v in regs.
//
// FINAL (= R8/R12, measured-best: bench 46.5us twice, cold 37.9-38.4us,
// DRAM ~72% vs a ~36-37.5us mixed R/W floor for 256MB mandatory traffic).
// Full search, all rejected by measurement:
//   - .cs stores: forced 128MB DRAM writeback per graph replay (bench -4us)
//   - evict_last 1.0: 128MB pinned > 126MB L2, thrashed (bench -7us)
//   - evict_last 0.5: still lost to default replacement (bench -4us)
//   - 128-thread blocks: neutral-worse (wave imbalance not binding)
//   - float2 / 2x occupancy: DRAM% fell (latency hiding already sufficient)
//   - PF=8: collapsed by ptxas, neutral
//   - 4-step burst grouping: +39 regs, occ fell, DRAM fell (LTS reorders
//     the stream anyway; per-thread grouping doesn't reach the controller)

#define LIF_N 64
#define LIF_T 64
#define LIF_D 8192
#define LIF_D4 (LIF_D / 4)          // 2048 float4 per row
#define THREADS 256
#define PF 6                        // prefetch depth

__global__ __launch_bounds__(THREADS)
void momentum_lif_kernel(const float4* __restrict__ x,
                         const float* __restrict__ p_mom,
                         const float* __restrict__ p_lamb,
                         float4* __restrict__ out) {
    const float mom = __ldg(p_mom);
    const float lb  = __ldg(p_lamb);

    int idx = blockIdx.x * THREADS + threadIdx.x;   // 0 .. N*D4-1 (exact grid)
    int n  = idx >> 11;          // idx / 2048
    int d4 = idx & 2047;         // idx % 2048

    const float4* xp = x   + (size_t)n * LIF_T * LIF_D4 + d4;
    float4*       op = out + (size_t)n * LIF_T * LIF_D4 + d4;

    float ux = 0.f, uy = 0.f, uz = 0.f, uw = 0.f;
    float vx = 0.f, vy = 0.f, vz = 0.f, vw = 0.f;

    // Prime the pipeline: PF independent loads in flight before any compute.
    float4 buf[PF];
#pragma unroll
    for (int i = 0; i < PF; ++i)
        buf[i] = xp[(size_t)i * LIF_D4];

#pragma unroll
    for (int t = 0; t < LIF_T; ++t) {
        float4 xv = buf[t % PF];
        // Refill the slot before the dependent math so the load overlaps
        // this iteration's compute + store.
        if (t + PF < LIF_T)
            buf[t % PF] = xp[(size_t)(t + PF) * LIF_D4];

        // lane x
        vx = fmaf(mom, vx, xv.x);
        vx = fmaf(-lb, ux, vx);
        ux = fmaf(0.5f, ux, vx);
        float sx = (ux >= 1.0f) ? 1.0f : 0.0f;
        ux = (ux >= 1.0f) ? 0.0f : ux;
        // lane y
        vy = fmaf(mom, vy, xv.y);
        vy = fmaf(-lb, uy, vy);
        uy = fmaf(0.5f, uy, vy);
        float sy = (uy >= 1.0f) ? 1.0f : 0.0f;
        uy = (uy >= 1.0f) ? 0.0f : uy;
        // lane z
        vz = fmaf(mom, vz, xv.z);
        vz = fmaf(-lb, uz, vz);
        uz = fmaf(0.5f, uz, vz);
        float sz = (uz >= 1.0f) ? 1.0f : 0.0f;
        uz = (uz >= 1.0f) ? 0.0f : uz;
        // lane w
        vw = fmaf(mom, vw, xv.w);
        vw = fmaf(-lb, uw, vw);
        uw = fmaf(0.5f, uw, vw);
        float sw = (uw >= 1.0f) ? 1.0f : 0.0f;
        uw = (uw >= 1.0f) ? 0.0f : uw;

        op[(size_t)t * LIF_D4] = make_float4(sx, sy, sz, sw);   // plain store
    }
}

extern "C" void kernel_launch(void* const* d_in, const int* in_sizes, int n_in,
                              void* d_out, int out_size) {
    const float4* x      = (const float4*)d_in[0];
    const float*  p_mom  = (const float*)d_in[1];
    const float*  p_lamb = (const float*)d_in[2];
    float4*       out    = (float4*)d_out;

    const int total = LIF_N * LIF_D4;           // 131072 threads
    momentum_lif_kernel<<<total / THREADS, THREADS>>>(x, p_mom, p_lamb, out);
}